// round 13
// baseline (speedup 1.0000x reference)
#include <cuda_runtime.h>
#include <cuda_fp16.h>

// ---------------------------------------------------------------------------
// PairWiseCrossAttention (B=8, N=1024, D=768, H=12, HD=64) — Round 13:
// R11 GEMM (128x128, 512 thr, best measured) with ONE change: LDG prefetch
// distance extended to 2 iterations via two register sets.
// R12's 128x64 tile reverted (regressed). Attention byte-identical.
// ---------------------------------------------------------------------------

#define Bsz   8
#define Ntok  1024
#define Dmod  768
#define Hn    12
#define HDim  64
#define N2    2048
#define MROWS 8192

__device__ __half g_Q  [(size_t)Bsz * Hn * Ntok * HDim];
__device__ __half g_K  [(size_t)Bsz * Hn * N2   * HDim];
__device__ __half g_V  [(size_t)Bsz * Hn * N2   * HDim];
__device__ __half g_ctx[(size_t)Bsz * Ntok * Dmod];

#define QSC 0.1803368801111204f   // 0.125 * log2(e): softmax in exp2 domain

__device__ __forceinline__ unsigned smaddr(const void* p) {
    return (unsigned)__cvta_generic_to_shared(p);
}
__device__ __forceinline__ void ldsm4(unsigned* r, const void* p) {
    asm volatile("ldmatrix.sync.aligned.m8n8.x4.shared.b16 {%0,%1,%2,%3},[%4];"
        : "=r"(r[0]), "=r"(r[1]), "=r"(r[2]), "=r"(r[3]) : "r"(smaddr(p)));
}
__device__ __forceinline__ void ldsm4t(unsigned* r, const void* p) {
    asm volatile("ldmatrix.sync.aligned.m8n8.x4.trans.shared.b16 {%0,%1,%2,%3},[%4];"
        : "=r"(r[0]), "=r"(r[1]), "=r"(r[2]), "=r"(r[3]) : "r"(smaddr(p)));
}
__device__ __forceinline__ void mma16816(float* c, const unsigned* a, const unsigned* b) {
    asm volatile("mma.sync.aligned.m16n8k16.row.col.f32.f16.f16.f32 "
        "{%0,%1,%2,%3},{%4,%5,%6,%7},{%8,%9},{%0,%1,%2,%3};"
        : "+f"(c[0]), "+f"(c[1]), "+f"(c[2]), "+f"(c[3])
        : "r"(a[0]), "r"(a[1]), "r"(a[2]), "r"(a[3]), "r"(b[0]), "r"(b[1]));
}
__device__ __forceinline__ unsigned h2pack(float x, float y) {
    __half2 h = __floats2half2_rn(x, y);
    return *(unsigned*)&h;
}
__device__ __forceinline__ void cpasync16(void* dst, const void* src) {
    asm volatile("cp.async.cg.shared.global [%0],[%1],16;" :: "r"(smaddr(dst)), "l"(src));
}

// ---------------------------------------------------------------------------
// GEMM: C = A @ W^T (+bias). 128x128 block, BK=32, 512 threads (16 warps,
// 4x4 warp grid, 32x32 warp tiles). Double-buffered smem, 1 barrier/tile,
// 2-iteration LDG prefetch distance (two register sets).
// mode 0: A=g_ctx (fp16) -> Cout fp32 + bias
// mode 1: A=x1           -> g_Q heads (scaled by QSC)
// mode 2/3: A=[x1;x2]    -> g_K / g_V heads
// ---------------------------------------------------------------------------
#define GBM 128
#define GBN 128
#define GBK 32
#define AST 40    // smem stride (halves): 80B rows, ldmatrix conflict-free (proven)
#define NKIT 24   // 768/32

// Loader: r = tid>>2 (row 0..127), fq = (tid&3)*8; thread owns floats
// [fq, fq+8) of its row for both A and B tiles. Two register sets (ss).
#define LOAD_REGS(ss, kbase) do {                                                \
    if (mode == 0) {                                                             \
        pah[ss] = *(const uint4*)(Ah + (size_t)(m0 + r) * Dmod + (kbase) + fq);  \
    } else {                                                                     \
        pa[ss][0] = *(const float4*)(A + (size_t)(mrow + r) * Dmod + (kbase) + fq);    \
        pa[ss][1] = *(const float4*)(A + (size_t)(mrow + r) * Dmod + (kbase) + fq + 4);\
    }                                                                            \
    pb[ss][0] = *(const float4*)(W + (size_t)(n0 + r) * Dmod + (kbase) + fq);    \
    pb[ss][1] = *(const float4*)(W + (size_t)(n0 + r) * Dmod + (kbase) + fq + 4);\
} while (0)

#define STS_STAGE(ss, st) do {                                                   \
    if (mode == 0) {                                                             \
        *(uint4*)&As[(st)][r][fq] = pah[ss];                                     \
    } else {                                                                     \
        uint4 wa = { h2pack(pa[ss][0].x, pa[ss][0].y), h2pack(pa[ss][0].z, pa[ss][0].w), \
                     h2pack(pa[ss][1].x, pa[ss][1].y), h2pack(pa[ss][1].z, pa[ss][1].w) };\
        *(uint4*)&As[(st)][r][fq] = wa;                                          \
    }                                                                            \
    {                                                                            \
        uint4 wb = { h2pack(pb[ss][0].x, pb[ss][0].y), h2pack(pb[ss][0].z, pb[ss][0].w), \
                     h2pack(pb[ss][1].x, pb[ss][1].y), h2pack(pb[ss][1].z, pb[ss][1].w) };\
        *(uint4*)&Bs[(st)][r][fq] = wb;                                          \
    }                                                                            \
} while (0)

__global__ __launch_bounds__(512)
void gemm_h(const float* __restrict__ A0, const float* __restrict__ A1,
            const float* __restrict__ W,  const float* __restrict__ bias,
            float* __restrict__ Cout, int mode)
{
    __shared__ __half As[2][GBM][AST];
    __shared__ __half Bs[2][GBN][AST];

    const int tid  = threadIdx.x;
    const int lane = tid & 31, warp = tid >> 5;       // warp 0..15
    const int g = lane >> 2, tq = lane & 3;
    const int wm = warp >> 2, wn = warp & 3;          // 4 x 4 warp grid, 32x32 tiles
    const int m0 = blockIdx.y * GBM, n0 = blockIdx.x * GBN;

    const float* A = A0;
    int mrow = m0;
    if ((mode == 2 || mode == 3) && m0 >= MROWS) { A = A1; mrow = m0 - MROWS; }
    const __half* Ah = g_ctx;   // mode 0 source

    const int r  = tid >> 2;          // 0..127
    const int fq = (tid & 3) * 8;     // float/half offset within BK row

    float acc[2][4][4];
#pragma unroll
    for (int i = 0; i < 2; ++i)
#pragma unroll
        for (int j = 0; j < 4; ++j)
#pragma unroll
            for (int c = 0; c < 4; ++c) acc[i][j][c] = 0.f;

    float4 pa[2][2], pb[2][2];
    uint4  pah[2];

    // Prologue: tile 0 -> stage 0 via set 0; then preload tiles 1,2.
    // Convention: tile t uses register set t&1 and smem stage t&1.
    LOAD_REGS(0, 0);
    STS_STAGE(0, 0);
    __syncthreads();
    LOAD_REGS(1, GBK);        // tile 1 -> set 1
    LOAD_REGS(0, 2 * GBK);    // tile 2 -> set 0

    // Mainloop: at iter it, STS tile it+1 (set/stage (it+1)&1), then issue
    // LDG for tile it+3 into the just-freed set. LDG->STS distance = 2 iters.
    for (int it = 0; it < NKIT; ++it) {
        const int cur = it & 1;
        const int nxt = cur ^ 1;
        if (it + 1 < NKIT) STS_STAGE(nxt, nxt);              // store tile it+1
        if (it + 3 < NKIT) LOAD_REGS(nxt, (it + 3) * GBK);   // prefetch tile it+3

#pragma unroll
        for (int ks = 0; ks < 2; ++ks) {
            unsigned af[2][4], bf[4][2];
#pragma unroll
            for (int mi = 0; mi < 2; ++mi)
                ldsm4(af[mi], &As[cur][wm * 32 + mi * 16 + (lane & 15)][ks * 16 + (lane >> 4) * 8]);
#pragma unroll
            for (int pr = 0; pr < 2; ++pr) {
                unsigned t4[4];
                ldsm4(t4, &Bs[cur][wn * 32 + pr * 16 + (lane & 7) + ((lane >> 4) << 3)]
                           [ks * 16 + ((lane >> 3) & 1) * 8]);
                bf[2 * pr    ][0] = t4[0]; bf[2 * pr    ][1] = t4[1];
                bf[2 * pr + 1][0] = t4[2]; bf[2 * pr + 1][1] = t4[3];
            }
#pragma unroll
            for (int mi = 0; mi < 2; ++mi)
#pragma unroll
                for (int nj = 0; nj < 4; ++nj)
                    mma16816(acc[mi][nj], af[mi], bf[nj]);
        }
        __syncthreads();
    }

    // Epilogue (identical to R11)
#pragma unroll
    for (int mi = 0; mi < 2; ++mi) {
#pragma unroll
        for (int rr = 0; rr < 2; ++rr) {
            int gm = m0 + wm * 32 + 16 * mi + g + 8 * rr;
#pragma unroll
            for (int nj = 0; nj < 4; ++nj) {
                int gn = n0 + wn * 32 + 8 * nj + 2 * tq;
                float v0 = acc[mi][nj][2 * rr], v1 = acc[mi][nj][2 * rr + 1];
                if (mode == 0) {
                    float2 o = { v0 + bias[gn], v1 + bias[gn + 1] };
                    *(float2*)(Cout + (size_t)gm * Dmod + gn) = o;
                } else {
                    int hh = gn >> 6, dd = gn & 63;
                    if (mode == 1) {
                        int b = gm >> 10, tok = gm & 1023;
                        *(__half2*)(g_Q + (((size_t)(b * Hn + hh)) * Ntok + tok) * HDim + dd)
                            = __floats2half2_rn(v0 * QSC, v1 * QSC);
                    } else {
                        int b, seq;
                        if (gm < MROWS) { b = gm >> 10; seq = gm & 1023; }
                        else { int m2 = gm - MROWS; b = m2 >> 10; seq = Ntok + (m2 & 1023); }
                        __half* dst = (mode == 2) ? g_K : g_V;
                        *(__half2*)(dst + (((size_t)(b * Hn + hh)) * N2 + seq) * HDim + dd)
                            = __floats2half2_rn(v0, v1);
                    }
                }
            }
        }
    }
}

// ---------------------------------------------------------------------------
// Attention — byte-identical to Round 4/10/11/12 (measured ~208-212us).
// ---------------------------------------------------------------------------
#define KST 72

__global__ __launch_bounds__(128)
void attn_h()
{
    __shared__ __half Qs[64][KST];
    __shared__ __half Ks[2][64][KST];
    __shared__ __half Vs[2][64][KST];

    const int t = threadIdx.x, lane = t & 31, warp = t >> 5;
    const int g = lane >> 2, tq = lane & 3;
    const int q0 = blockIdx.x * 64, bh = blockIdx.y;
    const int b = bh / Hn, h = bh - b * Hn;

    const __half* Qg = g_Q + ((size_t)bh * Ntok + q0) * HDim;
    const __half* Kg = g_K + (size_t)bh * N2 * HDim;
    const __half* Vg = g_V + (size_t)bh * N2 * HDim;

    auto issue = [&](int buf, int k0) {
        for (int i = t; i < 512; i += 128) {
            int r = i >> 3, c = (i & 7) * 8;
            cpasync16(&Ks[buf][r][c], Kg + (size_t)(k0 + r) * HDim + c);
            cpasync16(&Vs[buf][r][c], Vg + (size_t)(k0 + r) * HDim + c);
        }
        asm volatile("cp.async.commit_group;");
    };
    issue(0, 0);

    for (int i = t; i < 512; i += 128) {
        int r = i >> 3, c = (i & 7) * 8;
        *(uint4*)&Qs[r][c] = *(const uint4*)(Qg + (size_t)r * HDim + c);
    }
    __syncthreads();

    unsigned qa[4][4];
#pragma unroll
    for (int ks = 0; ks < 4; ++ks)
        ldsm4(qa[ks], &Qs[16 * warp + (lane & 15)][ks * 16 + (lane >> 4) * 8]);

    float m0 = -1e30f, m1 = -1e30f, l0 = 0.f, l1 = 0.f;
    float O[8][4];
#pragma unroll
    for (int j = 0; j < 8; ++j)
#pragma unroll
        for (int c = 0; c < 4; ++c) O[j][c] = 0.f;

    for (int it = 0; it < 32; ++it) {
        const int buf = it & 1;
        if (it < 31) {
            issue(buf ^ 1, (it + 1) * 64);
            asm volatile("cp.async.wait_group 1;");
        } else {
            asm volatile("cp.async.wait_group 0;");
        }
        __syncthreads();

        float S[8][4];
#pragma unroll
        for (int j = 0; j < 8; ++j)
#pragma unroll
            for (int c = 0; c < 4; ++c) S[j][c] = 0.f;
#pragma unroll
        for (int ks = 0; ks < 4; ++ks) {
#pragma unroll
            for (int pr = 0; pr < 4; ++pr) {
                unsigned t4[4];
                ldsm4(t4, &Ks[buf][pr * 16 + (lane & 7) + ((lane >> 4) << 3)]
                           [ks * 16 + ((lane >> 3) & 1) * 8]);
                mma16816(S[2 * pr    ], qa[ks], t4);
                mma16816(S[2 * pr + 1], qa[ks], t4 + 2);
            }
        }

        float mt0 = -1e30f, mt1 = -1e30f;
#pragma unroll
        for (int j = 0; j < 8; ++j) {
            mt0 = fmaxf(mt0, fmaxf(S[j][0], S[j][1]));
            mt1 = fmaxf(mt1, fmaxf(S[j][2], S[j][3]));
        }
        mt0 = fmaxf(mt0, __shfl_xor_sync(0xffffffffu, mt0, 1));
        mt0 = fmaxf(mt0, __shfl_xor_sync(0xffffffffu, mt0, 2));
        mt1 = fmaxf(mt1, __shfl_xor_sync(0xffffffffu, mt1, 1));
        mt1 = fmaxf(mt1, __shfl_xor_sync(0xffffffffu, mt1, 2));
        float mn0 = fmaxf(m0, mt0), mn1 = fmaxf(m1, mt1);
        float a0 = exp2f(m0 - mn0), a1 = exp2f(m1 - mn1);
        float ls0 = 0.f, ls1 = 0.f;
#pragma unroll
        for (int j = 0; j < 8; ++j) {
            S[j][0] = exp2f(S[j][0] - mn0);
            S[j][1] = exp2f(S[j][1] - mn0);
            S[j][2] = exp2f(S[j][2] - mn1);
            S[j][3] = exp2f(S[j][3] - mn1);
            ls0 += S[j][0] + S[j][1];
            ls1 += S[j][2] + S[j][3];
        }
        ls0 += __shfl_xor_sync(0xffffffffu, ls0, 1);
        ls0 += __shfl_xor_sync(0xffffffffu, ls0, 2);
        ls1 += __shfl_xor_sync(0xffffffffu, ls1, 1);
        ls1 += __shfl_xor_sync(0xffffffffu, ls1, 2);
        l0 = l0 * a0 + ls0;  l1 = l1 * a1 + ls1;
        m0 = mn0;  m1 = mn1;
#pragma unroll
        for (int j = 0; j < 8; ++j) {
            O[j][0] *= a0; O[j][1] *= a0; O[j][2] *= a1; O[j][3] *= a1;
        }

        unsigned pf[4][4];
#pragma unroll
        for (int kc = 0; kc < 4; ++kc) {
            int j0 = 2 * kc, j1 = 2 * kc + 1;
            pf[kc][0] = h2pack(S[j0][0], S[j0][1]);
            pf[kc][1] = h2pack(S[j0][2], S[j0][3]);
            pf[kc][2] = h2pack(S[j1][0], S[j1][1]);
            pf[kc][3] = h2pack(S[j1][2], S[j1][3]);
        }

#pragma unroll
        for (int kc = 0; kc < 4; ++kc) {
#pragma unroll
            for (int pr = 0; pr < 4; ++pr) {
                unsigned t4[4];
                ldsm4t(t4, &Vs[buf][kc * 16 + (lane & 7) + ((lane >> 3) & 1) * 8]
                            [8 * (2 * pr + (lane >> 4))]);
                mma16816(O[2 * pr    ], pf[kc], t4);
                mma16816(O[2 * pr + 1], pf[kc], t4 + 2);
            }
        }
        __syncthreads();
    }

    float i0 = 1.f / l0, i1 = 1.f / l1;
    __half* d0 = g_ctx + ((size_t)(b * Ntok + q0 + 16 * warp + g    )) * Dmod + h * HDim;
    __half* d1 = g_ctx + ((size_t)(b * Ntok + q0 + 16 * warp + 8 + g)) * Dmod + h * HDim;
#pragma unroll
    for (int nj = 0; nj < 8; ++nj) {
        *(__half2*)(d0 + 8 * nj + 2 * tq) = __floats2half2_rn(O[nj][0] * i0, O[nj][1] * i0);
        *(__half2*)(d1 + 8 * nj + 2 * tq) = __floats2half2_rn(O[nj][2] * i1, O[nj][3] * i1);
    }
}

// ---------------------------------------------------------------------------
extern "C" void kernel_launch(void* const* d_in, const int* in_sizes, int n_in,
                              void* d_out, int out_size)
{
    const float* x1 = (const float*)d_in[0];
    const float* x2 = (const float*)d_in[1];
    const float* Wq = (const float*)d_in[2];
    const float* Wk = (const float*)d_in[3];
    const float* Wv = (const float*)d_in[4];
    const float* Wo = (const float*)d_in[5];
    const float* bo = (const float*)d_in[6];
    float* out = (float*)d_out;

    dim3 blk(512);
    dim3 gq (Dmod / GBN, MROWS / GBM);         // (6, 64)
    dim3 gkv(Dmod / GBN, 2 * MROWS / GBM);     // (6, 128)

    gemm_h<<<gq,  blk>>>(x1, nullptr, Wq, nullptr, nullptr, 1);   // Q (scaled)
    gemm_h<<<gkv, blk>>>(x1, x2,      Wk, nullptr, nullptr, 2);   // K (concat)
    gemm_h<<<gkv, blk>>>(x1, x2,      Wv, nullptr, nullptr, 3);   // V (concat)
    attn_h<<<dim3(Ntok / 64, Bsz * Hn), 128>>>();                 // ctx
    gemm_h<<<gq,  blk>>>(nullptr, nullptr, Wo, bo, out, 0);       // out proj
}

// round 15
// speedup vs baseline: 1.4964x; 1.4964x over previous
#include <cuda_runtime.h>
#include <cuda_fp16.h>

// ---------------------------------------------------------------------------
// PairWiseCrossAttention (B=8, N=1024, D=768, H=12, HD=64) — Round 15:
// R11 with ONE change: GEMM blocks use 1024 threads (32 warps, 16x32 warp
// tiles) on the same 128x128 tile -> 8 warps/SMSP, 16-reg accumulators,
// 8-reg loader prefetch (fits 64-reg cap, no spill).
// tcgen05 abandoned (harness targets sm_100 base, no 'a' features).
// Attention byte-identical (measured ~210us).
// ---------------------------------------------------------------------------

#define Bsz   8
#define Ntok  1024
#define Dmod  768
#define Hn    12
#define HDim  64
#define N2    2048
#define MROWS 8192

__device__ __half g_Q  [(size_t)Bsz * Hn * Ntok * HDim];
__device__ __half g_K  [(size_t)Bsz * Hn * N2   * HDim];
__device__ __half g_V  [(size_t)Bsz * Hn * N2   * HDim];
__device__ __half g_ctx[(size_t)Bsz * Ntok * Dmod];

#define QSC 0.1803368801111204f   // 0.125 * log2(e): softmax in exp2 domain

__device__ __forceinline__ unsigned smaddr(const void* p) {
    return (unsigned)__cvta_generic_to_shared(p);
}
__device__ __forceinline__ void ldsm4(unsigned* r, const void* p) {
    asm volatile("ldmatrix.sync.aligned.m8n8.x4.shared.b16 {%0,%1,%2,%3},[%4];"
        : "=r"(r[0]), "=r"(r[1]), "=r"(r[2]), "=r"(r[3]) : "r"(smaddr(p)));
}
__device__ __forceinline__ void ldsm4t(unsigned* r, const void* p) {
    asm volatile("ldmatrix.sync.aligned.m8n8.x4.trans.shared.b16 {%0,%1,%2,%3},[%4];"
        : "=r"(r[0]), "=r"(r[1]), "=r"(r[2]), "=r"(r[3]) : "r"(smaddr(p)));
}
__device__ __forceinline__ void mma16816(float* c, const unsigned* a, const unsigned* b) {
    asm volatile("mma.sync.aligned.m16n8k16.row.col.f32.f16.f16.f32 "
        "{%0,%1,%2,%3},{%4,%5,%6,%7},{%8,%9},{%0,%1,%2,%3};"
        : "+f"(c[0]), "+f"(c[1]), "+f"(c[2]), "+f"(c[3])
        : "r"(a[0]), "r"(a[1]), "r"(a[2]), "r"(a[3]), "r"(b[0]), "r"(b[1]));
}
__device__ __forceinline__ unsigned h2pack(float x, float y) {
    __half2 h = __floats2half2_rn(x, y);
    return *(unsigned*)&h;
}
__device__ __forceinline__ void cpasync16(void* dst, const void* src) {
    asm volatile("cp.async.cg.shared.global [%0],[%1],16;" :: "r"(smaddr(dst)), "l"(src));
}

// ---------------------------------------------------------------------------
// GEMM: C = A @ W^T (+bias). 128x128 block, BK=32, 1024 threads (32 warps,
// 8x4 warp grid, 16x32 warp tiles). Double-buffered smem, 1 barrier/tile.
// Loader: each thread owns ONE float4 (4 floats) of A and of B per stage.
// mode 0: A=g_ctx (fp16) -> Cout fp32 + bias
// mode 1: A=x1           -> g_Q heads (scaled by QSC)
// mode 2/3: A=[x1;x2]    -> g_K / g_V heads
// ---------------------------------------------------------------------------
#define GBM 128
#define GBN 128
#define GBK 32
#define AST 40    // smem stride (halves): 80B rows, ldmatrix conflict-free (proven)
#define NKIT 24   // 768/32

// r = tid>>3 (row 0..127), fc = (tid&7)*4 (float offset in BK row).
#define LOAD_REGS(kbase) do {                                                    \
    if (mode == 0) {                                                             \
        pah = *(const uint2*)(Ah + (size_t)(m0 + r) * Dmod + (kbase) + fc);      \
    } else {                                                                     \
        pa  = *(const float4*)(A + (size_t)(mrow + r) * Dmod + (kbase) + fc);    \
    }                                                                            \
    pb = *(const float4*)(W + (size_t)(n0 + r) * Dmod + (kbase) + fc);           \
} while (0)

#define STS_STAGE(st) do {                                                       \
    if (mode == 0) {                                                             \
        *(uint2*)&As[(st)][r][fc] = pah;                                         \
    } else {                                                                     \
        uint2 wa = { h2pack(pa.x, pa.y), h2pack(pa.z, pa.w) };                   \
        *(uint2*)&As[(st)][r][fc] = wa;                                          \
    }                                                                            \
    {                                                                            \
        uint2 wb = { h2pack(pb.x, pb.y), h2pack(pb.z, pb.w) };                   \
        *(uint2*)&Bs[(st)][r][fc] = wb;                                          \
    }                                                                            \
} while (0)

__global__ __launch_bounds__(1024)
void gemm_h(const float* __restrict__ A0, const float* __restrict__ A1,
            const float* __restrict__ W,  const float* __restrict__ bias,
            float* __restrict__ Cout, int mode)
{
    __shared__ __half As[2][GBM][AST];
    __shared__ __half Bs[2][GBN][AST];

    const int tid  = threadIdx.x;
    const int lane = tid & 31, warp = tid >> 5;       // warp 0..31
    const int g = lane >> 2, tq = lane & 3;
    const int wm = warp >> 2, wn = warp & 3;          // 8 x 4 warp grid, 16x32 tiles
    const int m0 = blockIdx.y * GBM, n0 = blockIdx.x * GBN;

    const float* A = A0;
    int mrow = m0;
    if ((mode == 2 || mode == 3) && m0 >= MROWS) { A = A1; mrow = m0 - MROWS; }
    const __half* Ah = g_ctx;   // mode 0 source

    const int r  = tid >> 3;          // 0..127
    const int fc = (tid & 7) * 4;     // float/half offset within BK row

    float acc[4][4];
#pragma unroll
    for (int j = 0; j < 4; ++j)
#pragma unroll
        for (int c = 0; c < 4; ++c) acc[j][c] = 0.f;

    float4 pa, pb;
    uint2  pah;

    // Prologue: tile 0 -> stage 0; prefetch tile 1 into regs.
    LOAD_REGS(0);
    STS_STAGE(0);
    __syncthreads();
    LOAD_REGS(GBK);

    // Mainloop: tile it in stage it&1. STS(it+1) first (frees prefetch regs),
    // LDG(it+2) issued before mma so it drains under tensor work, 1 bar/iter.
    for (int it = 0; it < NKIT; ++it) {
        const int cur = it & 1;
        if (it + 1 < NKIT) STS_STAGE(cur ^ 1);          // store tile it+1
        if (it + 2 < NKIT) LOAD_REGS((it + 2) * GBK);   // prefetch tile it+2

#pragma unroll
        for (int ks = 0; ks < 2; ++ks) {
            unsigned af[4], bf[4][2];
            ldsm4(af, &As[cur][wm * 16 + (lane & 15)][ks * 16 + (lane >> 4) * 8]);
#pragma unroll
            for (int pr = 0; pr < 2; ++pr) {
                unsigned t4[4];
                ldsm4(t4, &Bs[cur][wn * 32 + pr * 16 + (lane & 7) + ((lane >> 4) << 3)]
                           [ks * 16 + ((lane >> 3) & 1) * 8]);
                bf[2 * pr    ][0] = t4[0]; bf[2 * pr    ][1] = t4[1];
                bf[2 * pr + 1][0] = t4[2]; bf[2 * pr + 1][1] = t4[3];
            }
#pragma unroll
            for (int nj = 0; nj < 4; ++nj)
                mma16816(acc[nj], af, bf[nj]);
        }
        __syncthreads();
    }

    // Epilogue (warp tile 16x32)
#pragma unroll
    for (int rr = 0; rr < 2; ++rr) {
        int gm = m0 + wm * 16 + g + 8 * rr;
#pragma unroll
        for (int nj = 0; nj < 4; ++nj) {
            int gn = n0 + wn * 32 + 8 * nj + 2 * tq;
            float v0 = acc[nj][2 * rr], v1 = acc[nj][2 * rr + 1];
            if (mode == 0) {
                float2 o = { v0 + bias[gn], v1 + bias[gn + 1] };
                *(float2*)(Cout + (size_t)gm * Dmod + gn) = o;
            } else {
                int hh = gn >> 6, dd = gn & 63;
                if (mode == 1) {
                    int b = gm >> 10, tok = gm & 1023;
                    *(__half2*)(g_Q + (((size_t)(b * Hn + hh)) * Ntok + tok) * HDim + dd)
                        = __floats2half2_rn(v0 * QSC, v1 * QSC);
                } else {
                    int b, seq;
                    if (gm < MROWS) { b = gm >> 10; seq = gm & 1023; }
                    else { int m2 = gm - MROWS; b = m2 >> 10; seq = Ntok + (m2 & 1023); }
                    __half* dst = (mode == 2) ? g_K : g_V;
                    *(__half2*)(dst + (((size_t)(b * Hn + hh)) * N2 + seq) * HDim + dd)
                        = __floats2half2_rn(v0, v1);
                }
            }
        }
    }
}

// ---------------------------------------------------------------------------
// Attention — byte-identical to Round 4/11 (measured ~210us).
// ---------------------------------------------------------------------------
#define KST 72

__global__ __launch_bounds__(128)
void attn_h()
{
    __shared__ __half Qs[64][KST];
    __shared__ __half Ks[2][64][KST];
    __shared__ __half Vs[2][64][KST];

    const int t = threadIdx.x, lane = t & 31, warp = t >> 5;
    const int g = lane >> 2, tq = lane & 3;
    const int q0 = blockIdx.x * 64, bh = blockIdx.y;
    const int b = bh / Hn, h = bh - b * Hn;

    const __half* Qg = g_Q + ((size_t)bh * Ntok + q0) * HDim;
    const __half* Kg = g_K + (size_t)bh * N2 * HDim;
    const __half* Vg = g_V + (size_t)bh * N2 * HDim;

    auto issue = [&](int buf, int k0) {
        for (int i = t; i < 512; i += 128) {
            int r = i >> 3, c = (i & 7) * 8;
            cpasync16(&Ks[buf][r][c], Kg + (size_t)(k0 + r) * HDim + c);
            cpasync16(&Vs[buf][r][c], Vg + (size_t)(k0 + r) * HDim + c);
        }
        asm volatile("cp.async.commit_group;");
    };
    issue(0, 0);

    for (int i = t; i < 512; i += 128) {
        int r = i >> 3, c = (i & 7) * 8;
        *(uint4*)&Qs[r][c] = *(const uint4*)(Qg + (size_t)r * HDim + c);
    }
    __syncthreads();

    unsigned qa[4][4];
#pragma unroll
    for (int ks = 0; ks < 4; ++ks)
        ldsm4(qa[ks], &Qs[16 * warp + (lane & 15)][ks * 16 + (lane >> 4) * 8]);

    float m0 = -1e30f, m1 = -1e30f, l0 = 0.f, l1 = 0.f;
    float O[8][4];
#pragma unroll
    for (int j = 0; j < 8; ++j)
#pragma unroll
        for (int c = 0; c < 4; ++c) O[j][c] = 0.f;

    for (int it = 0; it < 32; ++it) {
        const int buf = it & 1;
        if (it < 31) {
            issue(buf ^ 1, (it + 1) * 64);
            asm volatile("cp.async.wait_group 1;");
        } else {
            asm volatile("cp.async.wait_group 0;");
        }
        __syncthreads();

        float S[8][4];
#pragma unroll
        for (int j = 0; j < 8; ++j)
#pragma unroll
            for (int c = 0; c < 4; ++c) S[j][c] = 0.f;
#pragma unroll
        for (int ks = 0; ks < 4; ++ks) {
#pragma unroll
            for (int pr = 0; pr < 4; ++pr) {
                unsigned t4[4];
                ldsm4(t4, &Ks[buf][pr * 16 + (lane & 7) + ((lane >> 4) << 3)]
                           [ks * 16 + ((lane >> 3) & 1) * 8]);
                mma16816(S[2 * pr    ], qa[ks], t4);
                mma16816(S[2 * pr + 1], qa[ks], t4 + 2);
            }
        }

        float mt0 = -1e30f, mt1 = -1e30f;
#pragma unroll
        for (int j = 0; j < 8; ++j) {
            mt0 = fmaxf(mt0, fmaxf(S[j][0], S[j][1]));
            mt1 = fmaxf(mt1, fmaxf(S[j][2], S[j][3]));
        }
        mt0 = fmaxf(mt0, __shfl_xor_sync(0xffffffffu, mt0, 1));
        mt0 = fmaxf(mt0, __shfl_xor_sync(0xffffffffu, mt0, 2));
        mt1 = fmaxf(mt1, __shfl_xor_sync(0xffffffffu, mt1, 1));
        mt1 = fmaxf(mt1, __shfl_xor_sync(0xffffffffu, mt1, 2));
        float mn0 = fmaxf(m0, mt0), mn1 = fmaxf(m1, mt1);
        float a0 = exp2f(m0 - mn0), a1 = exp2f(m1 - mn1);
        float ls0 = 0.f, ls1 = 0.f;
#pragma unroll
        for (int j = 0; j < 8; ++j) {
            S[j][0] = exp2f(S[j][0] - mn0);
            S[j][1] = exp2f(S[j][1] - mn0);
            S[j][2] = exp2f(S[j][2] - mn1);
            S[j][3] = exp2f(S[j][3] - mn1);
            ls0 += S[j][0] + S[j][1];
            ls1 += S[j][2] + S[j][3];
        }
        ls0 += __shfl_xor_sync(0xffffffffu, ls0, 1);
        ls0 += __shfl_xor_sync(0xffffffffu, ls0, 2);
        ls1 += __shfl_xor_sync(0xffffffffu, ls1, 1);
        ls1 += __shfl_xor_sync(0xffffffffu, ls1, 2);
        l0 = l0 * a0 + ls0;  l1 = l1 * a1 + ls1;
        m0 = mn0;  m1 = mn1;
#pragma unroll
        for (int j = 0; j < 8; ++j) {
            O[j][0] *= a0; O[j][1] *= a0; O[j][2] *= a1; O[j][3] *= a1;
        }

        unsigned pf[4][4];
#pragma unroll
        for (int kc = 0; kc < 4; ++kc) {
            int j0 = 2 * kc, j1 = 2 * kc + 1;
            pf[kc][0] = h2pack(S[j0][0], S[j0][1]);
            pf[kc][1] = h2pack(S[j0][2], S[j0][3]);
            pf[kc][2] = h2pack(S[j1][0], S[j1][1]);
            pf[kc][3] = h2pack(S[j1][2], S[j1][3]);
        }

#pragma unroll
        for (int kc = 0; kc < 4; ++kc) {
#pragma unroll
            for (int pr = 0; pr < 4; ++pr) {
                unsigned t4[4];
                ldsm4t(t4, &Vs[buf][kc * 16 + (lane & 7) + ((lane >> 3) & 1) * 8]
                            [8 * (2 * pr + (lane >> 4))]);
                mma16816(O[2 * pr    ], pf[kc], t4);
                mma16816(O[2 * pr + 1], pf[kc], t4 + 2);
            }
        }
        __syncthreads();
    }

    float i0 = 1.f / l0, i1 = 1.f / l1;
    __half* d0 = g_ctx + ((size_t)(b * Ntok + q0 + 16 * warp + g    )) * Dmod + h * HDim;
    __half* d1 = g_ctx + ((size_t)(b * Ntok + q0 + 16 * warp + 8 + g)) * Dmod + h * HDim;
#pragma unroll
    for (int nj = 0; nj < 8; ++nj) {
        *(__half2*)(d0 + 8 * nj + 2 * tq) = __floats2half2_rn(O[nj][0] * i0, O[nj][1] * i0);
        *(__half2*)(d1 + 8 * nj + 2 * tq) = __floats2half2_rn(O[nj][2] * i1, O[nj][3] * i1);
    }
}

// ---------------------------------------------------------------------------
extern "C" void kernel_launch(void* const* d_in, const int* in_sizes, int n_in,
                              void* d_out, int out_size)
{
    const float* x1 = (const float*)d_in[0];
    const float* x2 = (const float*)d_in[1];
    const float* Wq = (const float*)d_in[2];
    const float* Wk = (const float*)d_in[3];
    const float* Wv = (const float*)d_in[4];
    const float* Wo = (const float*)d_in[5];
    const float* bo = (const float*)d_in[6];
    float* out = (float*)d_out;

    dim3 blk(1024);
    dim3 gq (Dmod / GBN, MROWS / GBM);         // (6, 64)
    dim3 gkv(Dmod / GBN, 2 * MROWS / GBM);     // (6, 128)

    gemm_h<<<gq,  blk>>>(x1, nullptr, Wq, nullptr, nullptr, 1);   // Q (scaled)
    gemm_h<<<gkv, blk>>>(x1, x2,      Wk, nullptr, nullptr, 2);   // K (concat)
    gemm_h<<<gkv, blk>>>(x1, x2,      Wv, nullptr, nullptr, 3);   // V (concat)
    attn_h<<<dim3(Ntok / 64, Bsz * Hn), 128>>>();                 // ctx
    gemm_h<<<gq,  blk>>>(nullptr, nullptr, Wo, bo, out, 0);       // out proj
}

// round 16
// speedup vs baseline: 1.6997x; 1.1359x over previous
#include <cuda_runtime.h>
#include <cuda_fp16.h>

// ---------------------------------------------------------------------------
// PairWiseCrossAttention (B=8, N=1024, D=768, H=12, HD=64) — Round 16:
// R11 GEMM body exactly (best measured: 571us total), with Q/K/V GEMMs fused
// into ONE 1920-block launch (kills 2 idle tail waves + 2 launch gaps).
// R15's 1024-thread variant reverted (595us). Attention byte-identical.
// ---------------------------------------------------------------------------

#define Bsz   8
#define Ntok  1024
#define Dmod  768
#define Hn    12
#define HDim  64
#define N2    2048
#define MROWS 8192

__device__ __half g_Q  [(size_t)Bsz * Hn * Ntok * HDim];
__device__ __half g_K  [(size_t)Bsz * Hn * N2   * HDim];
__device__ __half g_V  [(size_t)Bsz * Hn * N2   * HDim];
__device__ __half g_ctx[(size_t)Bsz * Ntok * Dmod];

#define QSC 0.1803368801111204f   // 0.125 * log2(e): softmax in exp2 domain

__device__ __forceinline__ unsigned smaddr(const void* p) {
    return (unsigned)__cvta_generic_to_shared(p);
}
__device__ __forceinline__ void ldsm4(unsigned* r, const void* p) {
    asm volatile("ldmatrix.sync.aligned.m8n8.x4.shared.b16 {%0,%1,%2,%3},[%4];"
        : "=r"(r[0]), "=r"(r[1]), "=r"(r[2]), "=r"(r[3]) : "r"(smaddr(p)));
}
__device__ __forceinline__ void ldsm4t(unsigned* r, const void* p) {
    asm volatile("ldmatrix.sync.aligned.m8n8.x4.trans.shared.b16 {%0,%1,%2,%3},[%4];"
        : "=r"(r[0]), "=r"(r[1]), "=r"(r[2]), "=r"(r[3]) : "r"(smaddr(p)));
}
__device__ __forceinline__ void mma16816(float* c, const unsigned* a, const unsigned* b) {
    asm volatile("mma.sync.aligned.m16n8k16.row.col.f32.f16.f16.f32 "
        "{%0,%1,%2,%3},{%4,%5,%6,%7},{%8,%9},{%0,%1,%2,%3};"
        : "+f"(c[0]), "+f"(c[1]), "+f"(c[2]), "+f"(c[3])
        : "r"(a[0]), "r"(a[1]), "r"(a[2]), "r"(a[3]), "r"(b[0]), "r"(b[1]));
}
__device__ __forceinline__ unsigned h2pack(float x, float y) {
    __half2 h = __floats2half2_rn(x, y);
    return *(unsigned*)&h;
}
__device__ __forceinline__ void cpasync16(void* dst, const void* src) {
    asm volatile("cp.async.cg.shared.global [%0],[%1],16;" :: "r"(smaddr(dst)), "l"(src));
}

// ---------------------------------------------------------------------------
// GEMM: C = A @ W^T (+bias). 128x128 block, BK=32, 512 threads (16 warps,
// 4x4 warp grid, 32x32 warp tiles). Double-buffered smem, 1 barrier/tile.
// fused=1: 1920 blocks decode to {Q, K, V}; fused=0: 384 blocks, out-proj.
// ---------------------------------------------------------------------------
#define GBM 128
#define GBN 128
#define GBK 32
#define AST 40    // smem stride (halves): 80B rows, ldmatrix conflict-free (proven)
#define NKIT 24   // 768/32

#define LOAD_REGS(kbase) do {                                                    \
    if (mode == 0) {                                                             \
        pah = *(const uint4*)(Ah + (size_t)(m0 + r) * Dmod + (kbase) + fq);      \
    } else {                                                                     \
        pa0 = *(const float4*)(A + (size_t)(mrow + r) * Dmod + (kbase) + fq);    \
        pa1 = *(const float4*)(A + (size_t)(mrow + r) * Dmod + (kbase) + fq + 4);\
    }                                                                            \
    pb0 = *(const float4*)(W + (size_t)(n0 + r) * Dmod + (kbase) + fq);          \
    pb1 = *(const float4*)(W + (size_t)(n0 + r) * Dmod + (kbase) + fq + 4);      \
} while (0)

#define STS_STAGE(st) do {                                                       \
    if (mode == 0) {                                                             \
        *(uint4*)&As[(st)][r][fq] = pah;                                         \
    } else {                                                                     \
        uint4 wa = { h2pack(pa0.x, pa0.y), h2pack(pa0.z, pa0.w),                 \
                     h2pack(pa1.x, pa1.y), h2pack(pa1.z, pa1.w) };               \
        *(uint4*)&As[(st)][r][fq] = wa;                                          \
    }                                                                            \
    {                                                                            \
        uint4 wb = { h2pack(pb0.x, pb0.y), h2pack(pb0.z, pb0.w),                 \
                     h2pack(pb1.x, pb1.y), h2pack(pb1.z, pb1.w) };               \
        *(uint4*)&Bs[(st)][r][fq] = wb;                                          \
    }                                                                            \
} while (0)

__global__ __launch_bounds__(512)
void gemm_h(const float* __restrict__ x1, const float* __restrict__ x2,
            const float* __restrict__ Wq, const float* __restrict__ Wk,
            const float* __restrict__ Wv, const float* __restrict__ bias,
            float* __restrict__ Cout, int fused)
{
    __shared__ __half As[2][GBM][AST];
    __shared__ __half Bs[2][GBN][AST];

    const int tid  = threadIdx.x;
    const int lane = tid & 31, warp = tid >> 5;       // warp 0..15
    const int g = lane >> 2, tq = lane & 3;
    const int wm = warp >> 2, wn = warp & 3;          // 4 x 4 warp grid, 32x32 tiles

    // Block decode: fused QKV (1920 blocks) or out-proj (384 blocks).
    const int id = blockIdx.x;
    int mode, sub;
    if (fused) {
        if (id < 384)       { mode = 1; sub = id; }
        else if (id < 1152) { mode = 2; sub = id - 384; }
        else                { mode = 3; sub = id - 1152; }
    } else { mode = 0; sub = id; }
    const int m0 = (sub / 6) * GBM;                   // Q/mode0: [0,8192); K/V: [0,16384)
    const int n0 = (sub % 6) * GBN;
    const float* W = (mode == 2) ? Wk : (mode == 3) ? Wv : Wq;  // mode0 passes Wo in Wq

    const float* A = x1;
    int mrow = m0;
    if ((mode == 2 || mode == 3) && m0 >= MROWS) { A = x2; mrow = m0 - MROWS; }
    const __half* Ah = g_ctx;   // mode 0 source

    const int r  = tid >> 2;          // 0..127
    const int fq = (tid & 3) * 8;     // float/half offset within BK row

    float acc[2][4][4];
#pragma unroll
    for (int i = 0; i < 2; ++i)
#pragma unroll
        for (int j = 0; j < 4; ++j)
#pragma unroll
            for (int c = 0; c < 4; ++c) acc[i][j][c] = 0.f;

    float4 pa0, pa1, pb0, pb1;
    uint4  pah;

    // Prologue: tile 0 -> stage 0; prefetch tile 1 into regs.
    LOAD_REGS(0);
    STS_STAGE(0);
    __syncthreads();
    LOAD_REGS(GBK);

    // Mainloop: tile it in stage it&1; one barrier per iteration.
    for (int it = 0; it < NKIT; ++it) {
        const int cur = it & 1;
        if (it + 1 < NKIT) STS_STAGE(cur ^ 1);          // store tile it+1
        if (it + 2 < NKIT) LOAD_REGS((it + 2) * GBK);   // prefetch tile it+2

#pragma unroll
        for (int ks = 0; ks < 2; ++ks) {
            unsigned af[2][4], bf[4][2];
#pragma unroll
            for (int mi = 0; mi < 2; ++mi)
                ldsm4(af[mi], &As[cur][wm * 32 + mi * 16 + (lane & 15)][ks * 16 + (lane >> 4) * 8]);
#pragma unroll
            for (int pr = 0; pr < 2; ++pr) {
                unsigned t4[4];
                ldsm4(t4, &Bs[cur][wn * 32 + pr * 16 + (lane & 7) + ((lane >> 4) << 3)]
                           [ks * 16 + ((lane >> 3) & 1) * 8]);
                bf[2 * pr    ][0] = t4[0]; bf[2 * pr    ][1] = t4[1];
                bf[2 * pr + 1][0] = t4[2]; bf[2 * pr + 1][1] = t4[3];
            }
#pragma unroll
            for (int mi = 0; mi < 2; ++mi)
#pragma unroll
                for (int nj = 0; nj < 4; ++nj)
                    mma16816(acc[mi][nj], af[mi], bf[nj]);
        }
        __syncthreads();
    }

    // Epilogue (identical to R11)
#pragma unroll
    for (int mi = 0; mi < 2; ++mi) {
#pragma unroll
        for (int rr = 0; rr < 2; ++rr) {
            int gm = m0 + wm * 32 + 16 * mi + g + 8 * rr;
#pragma unroll
            for (int nj = 0; nj < 4; ++nj) {
                int gn = n0 + wn * 32 + 8 * nj + 2 * tq;
                float v0 = acc[mi][nj][2 * rr], v1 = acc[mi][nj][2 * rr + 1];
                if (mode == 0) {
                    float2 o = { v0 + bias[gn], v1 + bias[gn + 1] };
                    *(float2*)(Cout + (size_t)gm * Dmod + gn) = o;
                } else {
                    int hh = gn >> 6, dd = gn & 63;
                    if (mode == 1) {
                        int b = gm >> 10, tok = gm & 1023;
                        *(__half2*)(g_Q + (((size_t)(b * Hn + hh)) * Ntok + tok) * HDim + dd)
                            = __floats2half2_rn(v0 * QSC, v1 * QSC);
                    } else {
                        int b, seq;
                        if (gm < MROWS) { b = gm >> 10; seq = gm & 1023; }
                        else { int m2 = gm - MROWS; b = m2 >> 10; seq = Ntok + (m2 & 1023); }
                        __half* dst = (mode == 2) ? g_K : g_V;
                        *(__half2*)(dst + (((size_t)(b * Hn + hh)) * N2 + seq) * HDim + dd)
                            = __floats2half2_rn(v0, v1);
                    }
                }
            }
        }
    }
}

// ---------------------------------------------------------------------------
// Attention — byte-identical to Round 4/11 (measured ~208-212us).
// ---------------------------------------------------------------------------
#define KST 72

__global__ __launch_bounds__(128)
void attn_h()
{
    __shared__ __half Qs[64][KST];
    __shared__ __half Ks[2][64][KST];
    __shared__ __half Vs[2][64][KST];

    const int t = threadIdx.x, lane = t & 31, warp = t >> 5;
    const int g = lane >> 2, tq = lane & 3;
    const int q0 = blockIdx.x * 64, bh = blockIdx.y;
    const int b = bh / Hn, h = bh - b * Hn;

    const __half* Qg = g_Q + ((size_t)bh * Ntok + q0) * HDim;
    const __half* Kg = g_K + (size_t)bh * N2 * HDim;
    const __half* Vg = g_V + (size_t)bh * N2 * HDim;

    auto issue = [&](int buf, int k0) {
        for (int i = t; i < 512; i += 128) {
            int r = i >> 3, c = (i & 7) * 8;
            cpasync16(&Ks[buf][r][c], Kg + (size_t)(k0 + r) * HDim + c);
            cpasync16(&Vs[buf][r][c], Vg + (size_t)(k0 + r) * HDim + c);
        }
        asm volatile("cp.async.commit_group;");
    };
    issue(0, 0);

    for (int i = t; i < 512; i += 128) {
        int r = i >> 3, c = (i & 7) * 8;
        *(uint4*)&Qs[r][c] = *(const uint4*)(Qg + (size_t)r * HDim + c);
    }
    __syncthreads();

    unsigned qa[4][4];
#pragma unroll
    for (int ks = 0; ks < 4; ++ks)
        ldsm4(qa[ks], &Qs[16 * warp + (lane & 15)][ks * 16 + (lane >> 4) * 8]);

    float m0 = -1e30f, m1 = -1e30f, l0 = 0.f, l1 = 0.f;
    float O[8][4];
#pragma unroll
    for (int j = 0; j < 8; ++j)
#pragma unroll
        for (int c = 0; c < 4; ++c) O[j][c] = 0.f;

    for (int it = 0; it < 32; ++it) {
        const int buf = it & 1;
        if (it < 31) {
            issue(buf ^ 1, (it + 1) * 64);
            asm volatile("cp.async.wait_group 1;");
        } else {
            asm volatile("cp.async.wait_group 0;");
        }
        __syncthreads();

        float S[8][4];
#pragma unroll
        for (int j = 0; j < 8; ++j)
#pragma unroll
            for (int c = 0; c < 4; ++c) S[j][c] = 0.f;
#pragma unroll
        for (int ks = 0; ks < 4; ++ks) {
#pragma unroll
            for (int pr = 0; pr < 4; ++pr) {
                unsigned t4[4];
                ldsm4(t4, &Ks[buf][pr * 16 + (lane & 7) + ((lane >> 4) << 3)]
                           [ks * 16 + ((lane >> 3) & 1) * 8]);
                mma16816(S[2 * pr    ], qa[ks], t4);
                mma16816(S[2 * pr + 1], qa[ks], t4 + 2);
            }
        }

        float mt0 = -1e30f, mt1 = -1e30f;
#pragma unroll
        for (int j = 0; j < 8; ++j) {
            mt0 = fmaxf(mt0, fmaxf(S[j][0], S[j][1]));
            mt1 = fmaxf(mt1, fmaxf(S[j][2], S[j][3]));
        }
        mt0 = fmaxf(mt0, __shfl_xor_sync(0xffffffffu, mt0, 1));
        mt0 = fmaxf(mt0, __shfl_xor_sync(0xffffffffu, mt0, 2));
        mt1 = fmaxf(mt1, __shfl_xor_sync(0xffffffffu, mt1, 1));
        mt1 = fmaxf(mt1, __shfl_xor_sync(0xffffffffu, mt1, 2));
        float mn0 = fmaxf(m0, mt0), mn1 = fmaxf(m1, mt1);
        float a0 = exp2f(m0 - mn0), a1 = exp2f(m1 - mn1);
        float ls0 = 0.f, ls1 = 0.f;
#pragma unroll
        for (int j = 0; j < 8; ++j) {
            S[j][0] = exp2f(S[j][0] - mn0);
            S[j][1] = exp2f(S[j][1] - mn0);
            S[j][2] = exp2f(S[j][2] - mn1);
            S[j][3] = exp2f(S[j][3] - mn1);
            ls0 += S[j][0] + S[j][1];
            ls1 += S[j][2] + S[j][3];
        }
        ls0 += __shfl_xor_sync(0xffffffffu, ls0, 1);
        ls0 += __shfl_xor_sync(0xffffffffu, ls0, 2);
        ls1 += __shfl_xor_sync(0xffffffffu, ls1, 1);
        ls1 += __shfl_xor_sync(0xffffffffu, ls1, 2);
        l0 = l0 * a0 + ls0;  l1 = l1 * a1 + ls1;
        m0 = mn0;  m1 = mn1;
#pragma unroll
        for (int j = 0; j < 8; ++j) {
            O[j][0] *= a0; O[j][1] *= a0; O[j][2] *= a1; O[j][3] *= a1;
        }

        unsigned pf[4][4];
#pragma unroll
        for (int kc = 0; kc < 4; ++kc) {
            int j0 = 2 * kc, j1 = 2 * kc + 1;
            pf[kc][0] = h2pack(S[j0][0], S[j0][1]);
            pf[kc][1] = h2pack(S[j0][2], S[j0][3]);
            pf[kc][2] = h2pack(S[j1][0], S[j1][1]);
            pf[kc][3] = h2pack(S[j1][2], S[j1][3]);
        }

#pragma unroll
        for (int kc = 0; kc < 4; ++kc) {
#pragma unroll
            for (int pr = 0; pr < 4; ++pr) {
                unsigned t4[4];
                ldsm4t(t4, &Vs[buf][kc * 16 + (lane & 7) + ((lane >> 3) & 1) * 8]
                            [8 * (2 * pr + (lane >> 4))]);
                mma16816(O[2 * pr    ], pf[kc], t4);
                mma16816(O[2 * pr + 1], pf[kc], t4 + 2);
            }
        }
        __syncthreads();
    }

    float i0 = 1.f / l0, i1 = 1.f / l1;
    __half* d0 = g_ctx + ((size_t)(b * Ntok + q0 + 16 * warp + g    )) * Dmod + h * HDim;
    __half* d1 = g_ctx + ((size_t)(b * Ntok + q0 + 16 * warp + 8 + g)) * Dmod + h * HDim;
#pragma unroll
    for (int nj = 0; nj < 8; ++nj) {
        *(__half2*)(d0 + 8 * nj + 2 * tq) = __floats2half2_rn(O[nj][0] * i0, O[nj][1] * i0);
        *(__half2*)(d1 + 8 * nj + 2 * tq) = __floats2half2_rn(O[nj][2] * i1, O[nj][3] * i1);
    }
}

// ---------------------------------------------------------------------------
extern "C" void kernel_launch(void* const* d_in, const int* in_sizes, int n_in,
                              void* d_out, int out_size)
{
    const float* x1 = (const float*)d_in[0];
    const float* x2 = (const float*)d_in[1];
    const float* Wq = (const float*)d_in[2];
    const float* Wk = (const float*)d_in[3];
    const float* Wv = (const float*)d_in[4];
    const float* Wo = (const float*)d_in[5];
    const float* bo = (const float*)d_in[6];
    float* out = (float*)d_out;

    // Fused Q+K+V GEMM: 1920 blocks (13 waves, ~0.2% tail).
    gemm_h<<<1920, 512>>>(x1, x2, Wq, Wk, Wv, nullptr, nullptr, 1);
    // Attention: ctx -> g_ctx.
    attn_h<<<dim3(Ntok / 64, Bsz * Hn), 128>>>();
    // Output projection (reads g_ctx; Wo passed in Wq slot).
    gemm_h<<<384, 512>>>(nullptr, nullptr, Wo, nullptr, nullptr, bo, out, 0);
}